// round 3
// baseline (speedup 1.0000x reference)
#include <cuda_runtime.h>
#include <cuda_bf16.h>
#include <math.h>

// ---------------------------------------------------------------------------
// SwinIRBlock: LN1 -> shifted-window MSA (rel-pos bias + shift mask) -> proj
//              + residual -> LN2 -> MLP(GELU) + residual
// B=16, H=W=128, C=192, WS=8, SHIFT=4, HEADS=6, HD=32, N=64
// All fp32. Shift / window partition / reverse folded into GEMM row maps.
// ---------------------------------------------------------------------------

#define TOKENS   262144          // B*H*W
#define CDIM     192
#define QKVDIM   576
#define MLPDIM   768
#define NWIN     4096            // B * 256
#define HEADS    6
#define HD       32
#define NPOS     64
#define SCALE    0.17677669529663687f   // 32^-0.5

// ---------------- scratch (static device arrays; no allocation) ------------
__device__ float g_ln  [ (size_t)TOKENS * CDIM   ];   // LN1 / LN2 output (reused)
__device__ float g_qkv [ (size_t)TOKENS * QKVDIM ];   // window-ordered qkv
__device__ float g_attn[ (size_t)TOKENS * CDIM   ];   // attention output (window order)
__device__ float g_h   [ (size_t)TOKENS * CDIM   ];   // h = shortcut + proj (token order)
__device__ float g_m1  [ (size_t)TOKENS * MLPDIM ];   // gelu(fc1)

// window-ordered row r -> token index (applies cyclic shift -4,-4 forward;
// same map is the scatter for window-reverse + roll(+4,+4))
__device__ __forceinline__ int map_shift_row(int r) {
    int win = r >> 6, n = r & 63;
    int b  = win >> 8;
    int wi = win & 255;
    int wh = wi >> 4, ww = wi & 15;
    int hh = (wh << 3) + (n >> 3);
    int wp = (ww << 3) + (n & 7);
    int hs = (hh + 4) & 127;
    int ws = (wp + 4) & 127;
    return (b << 14) + (hs << 7) + ws;
}

// ---------------------------- LayerNorm ------------------------------------
__global__ void __launch_bounds__(256)
ln_kernel(const float* __restrict__ x, const float* __restrict__ g,
          const float* __restrict__ b, float* __restrict__ y)
{
    int token = blockIdx.x * 8 + (threadIdx.x >> 5);
    int lane  = threadIdx.x & 31;
    const float* xp = x + (size_t)token * CDIM;

    float v[6];
    float s = 0.f;
#pragma unroll
    for (int i = 0; i < 6; i++) { v[i] = xp[lane + i * 32]; s += v[i]; }
#pragma unroll
    for (int o = 16; o > 0; o >>= 1) s += __shfl_xor_sync(0xffffffffu, s, o);
    float mean = s * (1.f / 192.f);

    float s2 = 0.f;
#pragma unroll
    for (int i = 0; i < 6; i++) { float d = v[i] - mean; s2 += d * d; }
#pragma unroll
    for (int o = 16; o > 0; o >>= 1) s2 += __shfl_xor_sync(0xffffffffu, s2, o);
    float rs = rsqrtf(s2 * (1.f / 192.f) + 1e-5f);

    float* yp = y + (size_t)token * CDIM;
#pragma unroll
    for (int i = 0; i < 6; i++) {
        int c = lane + i * 32;
        yp[c] = (v[i] - mean) * rs * g[c] + b[c];
    }
}

// ------------------------------ GEMM ---------------------------------------
// C[m,n] = sum_k A[row(m),k] * W[n,k] + bias[n]   (+ epilogue)
// BM=128 BN=64 BK=16, 128 threads, 8x8 register tile.
#define AM_DIRECT 0
#define AM_SHIFT  1
#define EPI_BIAS        0
#define EPI_GELU        1
#define EPI_RES_SCATTER 2   // out row = map_shift_row(m); add res[outrow]
#define EPI_RES_DIRECT  3   // add res[m]

template<int Kdim, int Ndim, int AMap, int Epi>
__global__ void __launch_bounds__(128)
gemm_kernel(const float* __restrict__ A, const float* __restrict__ W,
            const float* __restrict__ bias, const float* __restrict__ res,
            float* __restrict__ C)
{
    constexpr int BM = 128, BN = 64, BK = 16;
    __shared__ float As[BK][BM + 4];
    __shared__ float Ws[BK][BN + 4];

    const int tid = threadIdx.x;
    const int m0  = blockIdx.y * BM;
    const int n0  = blockIdx.x * BN;

    // per-thread fixed global-load assignments (rows fixed across k-tiles)
    const float* aptr[4]; int arow[4], akq[4];
#pragma unroll
    for (int i = 0; i < 4; i++) {
        int f = tid + i * 128;
        arow[i] = f >> 2; akq[i] = f & 3;
        int gr = m0 + arow[i];
        if (AMap == AM_SHIFT) gr = map_shift_row(gr);
        aptr[i] = A + (size_t)gr * Kdim + akq[i] * 4;
    }
    const float* wptr[2]; int wrow[2], wkq[2];
#pragma unroll
    for (int i = 0; i < 2; i++) {
        int f = tid + i * 128;
        wrow[i] = f >> 2; wkq[i] = f & 3;
        wptr[i] = W + (size_t)(n0 + wrow[i]) * Kdim + wkq[i] * 4;
    }

    const int tx = tid & 7;    // n-dir, 8 threads * 8 cols
    const int ty = tid >> 3;   // m-dir, 16 threads * 8 rows
    float acc[8][8] = {};

    for (int kt = 0; kt < Kdim; kt += BK) {
#pragma unroll
        for (int i = 0; i < 4; i++) {
            float4 v = *reinterpret_cast<const float4*>(aptr[i] + kt);
            As[akq[i] * 4 + 0][arow[i]] = v.x;
            As[akq[i] * 4 + 1][arow[i]] = v.y;
            As[akq[i] * 4 + 2][arow[i]] = v.z;
            As[akq[i] * 4 + 3][arow[i]] = v.w;
        }
#pragma unroll
        for (int i = 0; i < 2; i++) {
            float4 v = *reinterpret_cast<const float4*>(wptr[i] + kt);
            Ws[wkq[i] * 4 + 0][wrow[i]] = v.x;
            Ws[wkq[i] * 4 + 1][wrow[i]] = v.y;
            Ws[wkq[i] * 4 + 2][wrow[i]] = v.z;
            Ws[wkq[i] * 4 + 3][wrow[i]] = v.w;
        }
        __syncthreads();
#pragma unroll
        for (int k = 0; k < BK; k++) {
            float a[8], w[8];
            *reinterpret_cast<float4*>(&a[0]) = *reinterpret_cast<const float4*>(&As[k][ty * 8]);
            *reinterpret_cast<float4*>(&a[4]) = *reinterpret_cast<const float4*>(&As[k][ty * 8 + 4]);
            *reinterpret_cast<float4*>(&w[0]) = *reinterpret_cast<const float4*>(&Ws[k][tx * 8]);
            *reinterpret_cast<float4*>(&w[4]) = *reinterpret_cast<const float4*>(&Ws[k][tx * 8 + 4]);
#pragma unroll
            for (int i = 0; i < 8; i++)
#pragma unroll
                for (int j = 0; j < 8; j++)
                    acc[i][j] = fmaf(a[i], w[j], acc[i][j]);
        }
        __syncthreads();
    }

    // epilogue
    float bi[8];
#pragma unroll
    for (int j = 0; j < 8; j++) bi[j] = bias[n0 + tx * 8 + j];

#pragma unroll
    for (int i = 0; i < 8; i++) {
        int m = m0 + ty * 8 + i;
        int outrow = (Epi == EPI_RES_SCATTER) ? map_shift_row(m) : m;
        float* cp = C + (size_t)outrow * Ndim + n0 + tx * 8;
        const float* rp = (Epi == EPI_RES_SCATTER || Epi == EPI_RES_DIRECT)
                              ? res + (size_t)outrow * Ndim + n0 + tx * 8 : nullptr;
#pragma unroll
        for (int j = 0; j < 8; j++) {
            float v = acc[i][j] + bi[j];
            if (Epi == EPI_GELU)
                v = 0.5f * v * (1.f + erff(v * 0.70710678118654752f));
            if (Epi == EPI_RES_SCATTER || Epi == EPI_RES_DIRECT)
                v += rp[j];
            cp[j] = v;
        }
    }
}

// --------------------------- Attention -------------------------------------
// one 64-thread block per (window, head); thread = query row n
__global__ void __launch_bounds__(64)
attn_kernel(const float* __restrict__ qkv, const float* __restrict__ rpb,
            float* __restrict__ out)
{
    __shared__ float Ksm[64][36];
    __shared__ float Vsm[64][36];
    __shared__ float bsm[1350];      // (2*8-1)^2 * HEADS = 225*6

    const int head = blockIdx.x % HEADS;
    const int win  = blockIdx.x / HEADS;
    const int n    = threadIdx.x;

    for (int i = n; i < 1350; i += 64) bsm[i] = rpb[i];

    const float* base = qkv + (size_t)win * 64 * QKVDIM;
    const float* qp = base + n * QKVDIM + head * HD;
    const float* kp = qp + CDIM;
    const float* vp = qp + 2 * CDIM;

    float q[32];
#pragma unroll
    for (int d4 = 0; d4 < 8; d4++) {
        float4 kv = *reinterpret_cast<const float4*>(kp + d4 * 4);
        Ksm[n][d4 * 4 + 0] = kv.x; Ksm[n][d4 * 4 + 1] = kv.y;
        Ksm[n][d4 * 4 + 2] = kv.z; Ksm[n][d4 * 4 + 3] = kv.w;
        float4 vv = *reinterpret_cast<const float4*>(vp + d4 * 4);
        Vsm[n][d4 * 4 + 0] = vv.x; Vsm[n][d4 * 4 + 1] = vv.y;
        Vsm[n][d4 * 4 + 2] = vv.z; Vsm[n][d4 * 4 + 3] = vv.w;
        float4 qq = *reinterpret_cast<const float4*>(qp + d4 * 4);
        q[d4 * 4 + 0] = qq.x * SCALE; q[d4 * 4 + 1] = qq.y * SCALE;
        q[d4 * 4 + 2] = qq.z * SCALE; q[d4 * 4 + 3] = qq.w * SCALE;
    }
    __syncthreads();

    // shift-mask region ids (nonzero only for boundary windows wh==15 / ww==15)
    const int wi = win & 255, wh = wi >> 4, ww = wi & 15;
    const int i1 = n >> 3, j1 = n & 7;
    const int rh1 = (wh == 15) ? ((i1 < 4) ? 1 : 2) : 0;
    const int rw1 = (ww == 15) ? ((j1 < 4) ? 1 : 2) : 0;

    float s[64];
#pragma unroll
    for (int m = 0; m < 64; m++) {
        float dot = 0.f;
#pragma unroll
        for (int d4 = 0; d4 < 8; d4++) {
            float4 kk = *reinterpret_cast<const float4*>(&Ksm[m][d4 * 4]);
            dot = fmaf(q[d4 * 4 + 0], kk.x, dot);
            dot = fmaf(q[d4 * 4 + 1], kk.y, dot);
            dot = fmaf(q[d4 * 4 + 2], kk.z, dot);
            dot = fmaf(q[d4 * 4 + 3], kk.w, dot);
        }
        const int i2 = m >> 3, j2 = m & 7;
        float bias = bsm[((i1 - i2 + 7) * 15 + (j1 - j2 + 7)) * HEADS + head];
        const int rh2 = (wh == 15) ? ((i2 < 4) ? 1 : 2) : 0;
        const int rw2 = (ww == 15) ? ((j2 < 4) ? 1 : 2) : 0;
        float msk = (rh1 == rh2 && rw1 == rw2) ? 0.f : -100.f;
        s[m] = dot + bias + msk;
    }

    float mx = -1e30f;
#pragma unroll
    for (int m = 0; m < 64; m++) mx = fmaxf(mx, s[m]);
    float sum = 0.f;
#pragma unroll
    for (int m = 0; m < 64; m++) { s[m] = __expf(s[m] - mx); sum += s[m]; }
    float inv = 1.f / sum;

    float o[32] = {};
#pragma unroll
    for (int m = 0; m < 64; m++) {
        float p = s[m] * inv;
#pragma unroll
        for (int d4 = 0; d4 < 8; d4++) {
            float4 vv = *reinterpret_cast<const float4*>(&Vsm[m][d4 * 4]);
            o[d4 * 4 + 0] = fmaf(p, vv.x, o[d4 * 4 + 0]);
            o[d4 * 4 + 1] = fmaf(p, vv.y, o[d4 * 4 + 1]);
            o[d4 * 4 + 2] = fmaf(p, vv.z, o[d4 * 4 + 2]);
            o[d4 * 4 + 3] = fmaf(p, vv.w, o[d4 * 4 + 3]);
        }
    }

    float* op = out + (size_t)(win * 64 + n) * CDIM + head * HD;
#pragma unroll
    for (int d4 = 0; d4 < 8; d4++)
        *reinterpret_cast<float4*>(op + d4 * 4) =
            make_float4(o[d4 * 4 + 0], o[d4 * 4 + 1], o[d4 * 4 + 2], o[d4 * 4 + 3]);
}

// ---------------------------------------------------------------------------
extern "C" void kernel_launch(void* const* d_in, const int* in_sizes, int n_in,
                              void* d_out, int out_size)
{
    const float* x       = (const float*)d_in[0];
    const float* norm1_g = (const float*)d_in[1];
    const float* norm1_b = (const float*)d_in[2];
    const float* qkv_w   = (const float*)d_in[3];
    const float* qkv_b   = (const float*)d_in[4];
    const float* proj_w  = (const float*)d_in[5];
    const float* proj_b  = (const float*)d_in[6];
    const float* rpb     = (const float*)d_in[7];
    const float* norm2_g = (const float*)d_in[8];
    const float* norm2_b = (const float*)d_in[9];
    const float* fc1_w   = (const float*)d_in[10];
    const float* fc1_b   = (const float*)d_in[11];
    const float* fc2_w   = (const float*)d_in[12];
    const float* fc2_b   = (const float*)d_in[13];
    float* out = (float*)d_out;

    float *p_ln, *p_qkv, *p_attn, *p_h, *p_m1;
    cudaGetSymbolAddress((void**)&p_ln,   g_ln);
    cudaGetSymbolAddress((void**)&p_qkv,  g_qkv);
    cudaGetSymbolAddress((void**)&p_attn, g_attn);
    cudaGetSymbolAddress((void**)&p_h,    g_h);
    cudaGetSymbolAddress((void**)&p_m1,   g_m1);

    const dim3 gemmBlk(128);
    const dim3 gridQKV(QKVDIM / 64, TOKENS / 128);
    const dim3 gridC  (CDIM   / 64, TOKENS / 128);
    const dim3 gridM  (MLPDIM / 64, TOKENS / 128);

    // 1. LN1
    ln_kernel<<<TOKENS / 8, 256>>>(x, norm1_g, norm1_b, p_ln);
    // 2. QKV gemm with shifted-window row gather
    gemm_kernel<CDIM, QKVDIM, AM_SHIFT, EPI_BIAS>
        <<<gridQKV, gemmBlk>>>(p_ln, qkv_w, qkv_b, nullptr, p_qkv);
    // 3. windowed attention (bias + shift mask + softmax)
    attn_kernel<<<NWIN * HEADS, 64>>>(p_qkv, rpb, p_attn);
    // 4. proj gemm; scatter rows back (window reverse + roll) + shortcut residual
    gemm_kernel<CDIM, CDIM, AM_DIRECT, EPI_RES_SCATTER>
        <<<gridC, gemmBlk>>>(p_attn, proj_w, proj_b, x, p_h);
    // 5. LN2
    ln_kernel<<<TOKENS / 8, 256>>>(p_h, norm2_g, norm2_b, p_ln);
    // 6. FC1 + exact GELU
    gemm_kernel<CDIM, MLPDIM, AM_DIRECT, EPI_GELU>
        <<<gridM, gemmBlk>>>(p_ln, fc1_w, fc1_b, nullptr, p_m1);
    // 7. FC2 + residual h  -> d_out
    gemm_kernel<MLPDIM, CDIM, AM_DIRECT, EPI_RES_DIRECT>
        <<<gridC, gemmBlk>>>(p_m1, fc2_w, fc2_b, p_h, out);
}

// round 5
// speedup vs baseline: 1.1253x; 1.1253x over previous
#include <cuda_runtime.h>
#include <cuda_bf16.h>
#include <stdint.h>
#include <math.h>

// ---------------------------------------------------------------------------
// SwinIRBlock: LN1 -> shifted-window MSA (rel-pos bias + shift mask) -> proj
//              + residual -> LN2 -> MLP(GELU) + residual
// B=16, H=W=128, C=192, WS=8, SHIFT=4, HEADS=6, HD=32, N=64
// GEMMs on tensor cores via mma.sync tf32 with 3-term split (fp32-accurate).
// ---------------------------------------------------------------------------

#define TOKENS   262144          // B*H*W
#define CDIM     192
#define QKVDIM   576
#define MLPDIM   768
#define NWIN     4096            // B * 256
#define HEADS    6
#define HD       32
#define SCALE    0.17677669529663687f   // 32^-0.5

// ---------------- scratch (static device arrays; no allocation) ------------
__device__ float g_ln  [ (size_t)TOKENS * CDIM   ];
__device__ float g_qkv [ (size_t)TOKENS * QKVDIM ];
__device__ float g_attn[ (size_t)TOKENS * CDIM   ];
__device__ float g_h   [ (size_t)TOKENS * CDIM   ];
__device__ float g_m1  [ (size_t)TOKENS * MLPDIM ];

// window-ordered row r -> token index (cyclic shift -4,-4 gather; same map is
// the scatter for window-reverse + roll(+4,+4))
__device__ __forceinline__ int map_shift_row(int r) {
    int win = r >> 6, n = r & 63;
    int b  = win >> 8;
    int wi = win & 255;
    int wh = wi >> 4, ww = wi & 15;
    int hh = (wh << 3) + (n >> 3);
    int wp = (ww << 3) + (n & 7);
    int hs = (hh + 4) & 127;
    int ws = (wp + 4) & 127;
    return (b << 14) + (hs << 7) + ws;
}

// ---------------------------- LayerNorm ------------------------------------
__global__ void __launch_bounds__(256)
ln_kernel(const float* __restrict__ x, const float* __restrict__ g,
          const float* __restrict__ b, float* __restrict__ y)
{
    int token = blockIdx.x * 8 + (threadIdx.x >> 5);
    int lane  = threadIdx.x & 31;
    const float* xp = x + (size_t)token * CDIM;

    float v[6];
    float s = 0.f;
#pragma unroll
    for (int i = 0; i < 6; i++) { v[i] = xp[lane + i * 32]; s += v[i]; }
#pragma unroll
    for (int o = 16; o > 0; o >>= 1) s += __shfl_xor_sync(0xffffffffu, s, o);
    float mean = s * (1.f / 192.f);

    float s2 = 0.f;
#pragma unroll
    for (int i = 0; i < 6; i++) { float d = v[i] - mean; s2 += d * d; }
#pragma unroll
    for (int o = 16; o > 0; o >>= 1) s2 += __shfl_xor_sync(0xffffffffu, s2, o);
    float rs = rsqrtf(s2 * (1.f / 192.f) + 1e-5f);

    float* yp = y + (size_t)token * CDIM;
#pragma unroll
    for (int i = 0; i < 6; i++) {
        int c = lane + i * 32;
        yp[c] = (v[i] - mean) * rs * g[c] + b[c];
    }
}

// ------------------------- TF32 split helpers ------------------------------
__device__ __forceinline__ void tf32_split(float x, unsigned int& hi, unsigned int& lo) {
    unsigned int h;
    asm("cvt.rna.tf32.f32 %0, %1;" : "=r"(h) : "f"(x));
    float lf = x - __uint_as_float(h);
    unsigned int l;
    asm("cvt.rna.tf32.f32 %0, %1;" : "=r"(l) : "f"(lf));
    hi = h; lo = l;
}

#define MMA_TF32(d, a0, a1, a2, a3, b0, b1)                                   \
    asm volatile("mma.sync.aligned.m16n8k8.row.col.f32.tf32.tf32.f32 "        \
                 "{%0,%1,%2,%3}, {%4,%5,%6,%7}, {%8,%9}, {%0,%1,%2,%3};"      \
                 : "+f"(d[0]), "+f"(d[1]), "+f"(d[2]), "+f"(d[3])             \
                 : "r"(a0), "r"(a1), "r"(a2), "r"(a3), "r"(b0), "r"(b1))

// ------------------------------ GEMM ---------------------------------------
// C[m,n] = sum_k A[row(m),k] * W[n,k] + bias[n]  (+ epilogue)
// 256 threads = 8 warps (4x2); BM=128 BN=64 BK=16; warp tile 32x32.
#define AM_DIRECT 0
#define AM_SHIFT  1
#define EPI_BIAS        0
#define EPI_GELU        1
#define EPI_RES_SCATTER 2
#define EPI_RES_DIRECT  3

template<int Kdim, int Ndim, int AMap, int Epi>
__global__ void __launch_bounds__(256)
gemm_kernel(const float* __restrict__ A, const float* __restrict__ W,
            const float* __restrict__ bias, const float* __restrict__ res,
            float* __restrict__ C)
{
    constexpr int BM = 128, BN = 64, BK = 16;
    __shared__ float As[BK][BM + 8];   // row stride 136 (mod 32 == 8): conflict-free frags
    __shared__ float Ws[BK][BN + 8];   // row stride 72  (mod 32 == 8)

    const int tid  = threadIdx.x;
    const int lane = tid & 31;
    const int warp = tid >> 5;
    const int wm   = warp >> 1;     // 0..3  (m direction, 32 rows each)
    const int wn   = warp & 1;      // 0..1  (n direction, 32 cols each)
    const int m0   = blockIdx.y * BM;
    const int n0   = blockIdx.x * BN;

    // global loaders: A 128x16 = 512 float4 -> 2/thread; W 64x16 = 256 -> 1/thread
    const float* aptr[2]; int arow[2], akq[2];
#pragma unroll
    for (int i = 0; i < 2; i++) {
        int f = tid + i * 256;
        arow[i] = f >> 2; akq[i] = f & 3;
        int gr = m0 + arow[i];
        if (AMap == AM_SHIFT) gr = map_shift_row(gr);
        aptr[i] = A + (size_t)gr * Kdim + akq[i] * 4;
    }
    const int wrow = tid >> 2, wkq = tid & 3;
    const float* wptr = W + (size_t)(n0 + wrow) * Kdim + wkq * 4;

    float acc[2][4][4] = {};

    float4 av[2], wv;
#pragma unroll
    for (int i = 0; i < 2; i++) av[i] = *reinterpret_cast<const float4*>(aptr[i]);
    wv = *reinterpret_cast<const float4*>(wptr);

    const int r  = lane >> 2;
    const int kq = lane & 3;

    for (int kt = 0; kt < Kdim; kt += BK) {
        // stage current tile
#pragma unroll
        for (int i = 0; i < 2; i++) {
            As[akq[i] * 4 + 0][arow[i]] = av[i].x;
            As[akq[i] * 4 + 1][arow[i]] = av[i].y;
            As[akq[i] * 4 + 2][arow[i]] = av[i].z;
            As[akq[i] * 4 + 3][arow[i]] = av[i].w;
        }
        Ws[wkq * 4 + 0][wrow] = wv.x;
        Ws[wkq * 4 + 1][wrow] = wv.y;
        Ws[wkq * 4 + 2][wrow] = wv.z;
        Ws[wkq * 4 + 3][wrow] = wv.w;
        __syncthreads();

        // prefetch next tile into registers (hidden behind MMA work)
        if (kt + BK < Kdim) {
#pragma unroll
            for (int i = 0; i < 2; i++)
                av[i] = *reinterpret_cast<const float4*>(aptr[i] + kt + BK);
            wv = *reinterpret_cast<const float4*>(wptr + kt + BK);
        }

#pragma unroll
        for (int ks = 0; ks < 2; ks++) {
            const int kk = ks * 8;
            unsigned int ah[2][4], al[2][4], bh[4][2], bl[4][2];
#pragma unroll
            for (int mt = 0; mt < 2; mt++) {
                int mb = wm * 32 + mt * 16 + r;
                tf32_split(As[kk + kq    ][mb    ], ah[mt][0], al[mt][0]);
                tf32_split(As[kk + kq    ][mb + 8], ah[mt][1], al[mt][1]);
                tf32_split(As[kk + 4 + kq][mb    ], ah[mt][2], al[mt][2]);
                tf32_split(As[kk + 4 + kq][mb + 8], ah[mt][3], al[mt][3]);
            }
#pragma unroll
            for (int nt = 0; nt < 4; nt++) {
                int nb = wn * 32 + nt * 8 + r;
                tf32_split(Ws[kk + kq    ][nb], bh[nt][0], bl[nt][0]);
                tf32_split(Ws[kk + 4 + kq][nb], bh[nt][1], bl[nt][1]);
            }
#pragma unroll
            for (int mt = 0; mt < 2; mt++)
#pragma unroll
                for (int nt = 0; nt < 4; nt++) {
                    MMA_TF32(acc[mt][nt], ah[mt][0], ah[mt][1], ah[mt][2], ah[mt][3],
                             bh[nt][0], bh[nt][1]);
                    MMA_TF32(acc[mt][nt], ah[mt][0], ah[mt][1], ah[mt][2], ah[mt][3],
                             bl[nt][0], bl[nt][1]);
                    MMA_TF32(acc[mt][nt], al[mt][0], al[mt][1], al[mt][2], al[mt][3],
                             bh[nt][0], bh[nt][1]);
                }
        }
        __syncthreads();
    }

    // ----------------------------- epilogue --------------------------------
#pragma unroll
    for (int nt = 0; nt < 4; nt++) {
        const int col = n0 + wn * 32 + nt * 8 + (lane & 3) * 2;
        const float b0v = bias[col], b1v = bias[col + 1];
#pragma unroll
        for (int mt = 0; mt < 2; mt++) {
#pragma unroll
            for (int half = 0; half < 2; half++) {
                int m = m0 + wm * 32 + mt * 16 + (lane >> 2) + half * 8;
                float v0 = acc[mt][nt][half * 2 + 0] + b0v;
                float v1 = acc[mt][nt][half * 2 + 1] + b1v;
                if (Epi == EPI_GELU) {
                    v0 = 0.5f * v0 * (1.f + erff(v0 * 0.70710678118654752f));
                    v1 = 0.5f * v1 * (1.f + erff(v1 * 0.70710678118654752f));
                }
                int outrow = (Epi == EPI_RES_SCATTER) ? map_shift_row(m) : m;
                float* cp = C + (size_t)outrow * Ndim + col;
                if (Epi == EPI_RES_SCATTER || Epi == EPI_RES_DIRECT) {
                    float2 rr = *reinterpret_cast<const float2*>(
                        res + (size_t)outrow * Ndim + col);
                    v0 += rr.x; v1 += rr.y;
                }
                *reinterpret_cast<float2*>(cp) = make_float2(v0, v1);
            }
        }
    }
}

// --------------------------- Attention -------------------------------------
// one 64-thread block per (window, head); thread = query row n
__global__ void __launch_bounds__(64)
attn_kernel(const float* __restrict__ qkv, const float* __restrict__ rpb,
            float* __restrict__ out)
{
    __shared__ float Ksm[64][36];
    __shared__ float Vsm[64][36];
    __shared__ float bsm[1350];      // 225 * 6

    const int head = blockIdx.x % HEADS;
    const int win  = blockIdx.x / HEADS;
    const int n    = threadIdx.x;

    for (int i = n; i < 1350; i += 64) bsm[i] = rpb[i];

    const float* base = qkv + (size_t)win * 64 * QKVDIM;
    const float* qp = base + n * QKVDIM + head * HD;
    const float* kp = qp + CDIM;
    const float* vp = qp + 2 * CDIM;

    float q[32];
#pragma unroll
    for (int d4 = 0; d4 < 8; d4++) {
        float4 kv = *reinterpret_cast<const float4*>(kp + d4 * 4);
        Ksm[n][d4 * 4 + 0] = kv.x; Ksm[n][d4 * 4 + 1] = kv.y;
        Ksm[n][d4 * 4 + 2] = kv.z; Ksm[n][d4 * 4 + 3] = kv.w;
        float4 vv = *reinterpret_cast<const float4*>(vp + d4 * 4);
        Vsm[n][d4 * 4 + 0] = vv.x; Vsm[n][d4 * 4 + 1] = vv.y;
        Vsm[n][d4 * 4 + 2] = vv.z; Vsm[n][d4 * 4 + 3] = vv.w;
        float4 qq = *reinterpret_cast<const float4*>(qp + d4 * 4);
        q[d4 * 4 + 0] = qq.x * SCALE; q[d4 * 4 + 1] = qq.y * SCALE;
        q[d4 * 4 + 2] = qq.z * SCALE; q[d4 * 4 + 3] = qq.w * SCALE;
    }
    __syncthreads();

    const int wi = win & 255, wh = wi >> 4, ww = wi & 15;
    const int i1 = n >> 3, j1 = n & 7;
    const int rh1 = (wh == 15) ? ((i1 < 4) ? 1 : 2) : 0;
    const int rw1 = (ww == 15) ? ((j1 < 4) ? 1 : 2) : 0;

    float s[64];
#pragma unroll
    for (int m = 0; m < 64; m++) {
        float dot = 0.f;
#pragma unroll
        for (int d4 = 0; d4 < 8; d4++) {
            float4 kk = *reinterpret_cast<const float4*>(&Ksm[m][d4 * 4]);
            dot = fmaf(q[d4 * 4 + 0], kk.x, dot);
            dot = fmaf(q[d4 * 4 + 1], kk.y, dot);
            dot = fmaf(q[d4 * 4 + 2], kk.z, dot);
            dot = fmaf(q[d4 * 4 + 3], kk.w, dot);
        }
        const int i2 = m >> 3, j2 = m & 7;
        float bias = bsm[((i1 - i2 + 7) * 15 + (j1 - j2 + 7)) * HEADS + head];
        const int rh2 = (wh == 15) ? ((i2 < 4) ? 1 : 2) : 0;
        const int rw2 = (ww == 15) ? ((j2 < 4) ? 1 : 2) : 0;
        float msk = (rh1 == rh2 && rw1 == rw2) ? 0.f : -100.f;
        s[m] = dot + bias + msk;
    }

    float mx = -1e30f;
#pragma unroll
    for (int m = 0; m < 64; m++) mx = fmaxf(mx, s[m]);
    float sum = 0.f;
#pragma unroll
    for (int m = 0; m < 64; m++) { s[m] = __expf(s[m] - mx); sum += s[m]; }
    float inv = 1.f / sum;

    float o[32] = {};
#pragma unroll
    for (int m = 0; m < 64; m++) {
        float p = s[m] * inv;
#pragma unroll
        for (int d4 = 0; d4 < 8; d4++) {
            float4 vv = *reinterpret_cast<const float4*>(&Vsm[m][d4 * 4]);
            o[d4 * 4 + 0] = fmaf(p, vv.x, o[d4 * 4 + 0]);
            o[d4 * 4 + 1] = fmaf(p, vv.y, o[d4 * 4 + 1]);
            o[d4 * 4 + 2] = fmaf(p, vv.z, o[d4 * 4 + 2]);
            o[d4 * 4 + 3] = fmaf(p, vv.w, o[d4 * 4 + 3]);
        }
    }

    float* op = out + (size_t)(win * 64 + n) * CDIM + head * HD;
#pragma unroll
    for (int d4 = 0; d4 < 8; d4++)
        *reinterpret_cast<float4*>(op + d4 * 4) =
            make_float4(o[d4 * 4 + 0], o[d4 * 4 + 1], o[d4 * 4 + 2], o[d4 * 4 + 3]);
}

// ---------------------------------------------------------------------------
extern "C" void kernel_launch(void* const* d_in, const int* in_sizes, int n_in,
                              void* d_out, int out_size)
{
    const float* x       = (const float*)d_in[0];
    const float* norm1_g = (const float*)d_in[1];
    const float* norm1_b = (const float*)d_in[2];
    const float* qkv_w   = (const float*)d_in[3];
    const float* qkv_b   = (const float*)d_in[4];
    const float* proj_w  = (const float*)d_in[5];
    const float* proj_b  = (const float*)d_in[6];
    const float* rpb     = (const float*)d_in[7];
    const float* norm2_g = (const float*)d_in[8];
    const float* norm2_b = (const float*)d_in[9];
    const float* fc1_w   = (const float*)d_in[10];
    const float* fc1_b   = (const float*)d_in[11];
    const float* fc2_w   = (const float*)d_in[12];
    const float* fc2_b   = (const float*)d_in[13];
    float* out = (float*)d_out;

    float *p_ln, *p_qkv, *p_attn, *p_h, *p_m1;
    cudaGetSymbolAddress((void**)&p_ln,   g_ln);
    cudaGetSymbolAddress((void**)&p_qkv,  g_qkv);
    cudaGetSymbolAddress((void**)&p_attn, g_attn);
    cudaGetSymbolAddress((void**)&p_h,    g_h);
    cudaGetSymbolAddress((void**)&p_m1,   g_m1);

    const dim3 gemmBlk(256);
    const dim3 gridQKV(QKVDIM / 64, TOKENS / 128);
    const dim3 gridC  (CDIM   / 64, TOKENS / 128);
    const dim3 gridM  (MLPDIM / 64, TOKENS / 128);

    // 1. LN1
    ln_kernel<<<TOKENS / 8, 256>>>(x, norm1_g, norm1_b, p_ln);
    // 2. QKV gemm with shifted-window row gather
    gemm_kernel<CDIM, QKVDIM, AM_SHIFT, EPI_BIAS>
        <<<gridQKV, gemmBlk>>>(p_ln, qkv_w, qkv_b, nullptr, p_qkv);
    // 3. windowed attention (bias + shift mask + softmax)
    attn_kernel<<<NWIN * HEADS, 64>>>(p_qkv, rpb, p_attn);
    // 4. proj gemm; scatter rows back (window reverse + roll) + shortcut residual
    gemm_kernel<CDIM, CDIM, AM_DIRECT, EPI_RES_SCATTER>
        <<<gridC, gemmBlk>>>(p_attn, proj_w, proj_b, x, p_h);
    // 5. LN2
    ln_kernel<<<TOKENS / 8, 256>>>(p_h, norm2_g, norm2_b, p_ln);
    // 6. FC1 + exact GELU
    gemm_kernel<CDIM, MLPDIM, AM_DIRECT, EPI_GELU>
        <<<gridM, gemmBlk>>>(p_ln, fc1_w, fc1_b, nullptr, p_m1);
    // 7. FC2 + residual h  -> d_out
    gemm_kernel<MLPDIM, CDIM, AM_DIRECT, EPI_RES_DIRECT>
        <<<gridC, gemmBlk>>>(p_m1, fc2_w, fc2_b, p_h, out);
}

// round 6
// speedup vs baseline: 1.2502x; 1.1110x over previous
#include <cuda_runtime.h>
#include <cuda_bf16.h>
#include <stdint.h>
#include <math.h>

// ---------------------------------------------------------------------------
// SwinIRBlock: LN1 -> shifted-window MSA (rel-pos bias + shift mask) -> proj
//              + residual -> LN2 -> MLP(GELU) + residual
// GEMMs: mma.sync tf32, 3-term split precomputed at smem staging time.
// ---------------------------------------------------------------------------

#define TOKENS   262144          // B*H*W
#define CDIM     192
#define QKVDIM   576
#define MLPDIM   768
#define NWIN     4096            // B * 256
#define HEADS    6
#define HD       32
#define SCALE    0.17677669529663687f   // 32^-0.5

// ---------------- scratch (static device arrays; no allocation) ------------
__device__ float g_ln  [ (size_t)TOKENS * CDIM   ];
__device__ float g_qkv [ (size_t)TOKENS * QKVDIM ];
__device__ float g_attn[ (size_t)TOKENS * CDIM   ];
__device__ float g_h   [ (size_t)TOKENS * CDIM   ];
__device__ float g_m1  [ (size_t)TOKENS * MLPDIM ];

// window-ordered row r -> token index (cyclic shift -4,-4 gather; same map is
// the scatter for window-reverse + roll(+4,+4))
__device__ __forceinline__ int map_shift_row(int r) {
    int win = r >> 6, n = r & 63;
    int b  = win >> 8;
    int wi = win & 255;
    int wh = wi >> 4, ww = wi & 15;
    int hh = (wh << 3) + (n >> 3);
    int wp = (ww << 3) + (n & 7);
    int hs = (hh + 4) & 127;
    int ws = (wp + 4) & 127;
    return (b << 14) + (hs << 7) + ws;
}

// ---------------------------- LayerNorm ------------------------------------
__global__ void __launch_bounds__(256)
ln_kernel(const float* __restrict__ x, const float* __restrict__ g,
          const float* __restrict__ b, float* __restrict__ y)
{
    int token = blockIdx.x * 8 + (threadIdx.x >> 5);
    int lane  = threadIdx.x & 31;
    const float* xp = x + (size_t)token * CDIM;

    float v[6];
    float s = 0.f;
#pragma unroll
    for (int i = 0; i < 6; i++) { v[i] = xp[lane + i * 32]; s += v[i]; }
#pragma unroll
    for (int o = 16; o > 0; o >>= 1) s += __shfl_xor_sync(0xffffffffu, s, o);
    float mean = s * (1.f / 192.f);

    float s2 = 0.f;
#pragma unroll
    for (int i = 0; i < 6; i++) { float d = v[i] - mean; s2 += d * d; }
#pragma unroll
    for (int o = 16; o > 0; o >>= 1) s2 += __shfl_xor_sync(0xffffffffu, s2, o);
    float rs = rsqrtf(s2 * (1.f / 192.f) + 1e-5f);

    float* yp = y + (size_t)token * CDIM;
#pragma unroll
    for (int i = 0; i < 6; i++) {
        int c = lane + i * 32;
        yp[c] = (v[i] - mean) * rs * g[c] + b[c];
    }
}

// ------------------------- TF32 split helpers ------------------------------
__device__ __forceinline__ void tf32_split(float x, unsigned int& hi, unsigned int& lo) {
    unsigned int h;
    asm("cvt.rna.tf32.f32 %0, %1;" : "=r"(h) : "f"(x));
    float lf = x - __uint_as_float(h);
    unsigned int l;
    asm("cvt.rna.tf32.f32 %0, %1;" : "=r"(l) : "f"(lf));
    hi = h; lo = l;
}

#define MMA_TF32(d, a0, a1, a2, a3, b0, b1)                                   \
    asm volatile("mma.sync.aligned.m16n8k8.row.col.f32.tf32.tf32.f32 "        \
                 "{%0,%1,%2,%3}, {%4,%5,%6,%7}, {%8,%9}, {%0,%1,%2,%3};"      \
                 : "+f"(d[0]), "+f"(d[1]), "+f"(d[2]), "+f"(d[3])             \
                 : "r"(a0), "r"(a1), "r"(a2), "r"(a3), "r"(b0), "r"(b1))

// XOR swizzle: decorrelates the k-quad from the column so staging stores hit
// 32 distinct banks; (k>>2) is constant per fragment-load instruction, so
// loads stay conflict-free as well.
#define SW(k, c) ((c) ^ ((((k) >> 2) & 3) << 3))

// ------------------------------ GEMM ---------------------------------------
// C[m,n] = sum_k A[row(m),k] * W[n,k] + bias[n]  (+ epilogue)
// 256 threads = 8 warps (4x2); BM=128 BN=64 BK=16; warp tile 32x32.
#define AM_DIRECT 0
#define AM_SHIFT  1
#define EPI_BIAS        0
#define EPI_GELU        1
#define EPI_RES_SCATTER 2
#define EPI_RES_DIRECT  3

template<int Kdim, int Ndim, int AMap, int Epi>
__global__ void __launch_bounds__(256)
gemm_kernel(const float* __restrict__ A, const float* __restrict__ W,
            const float* __restrict__ bias, const float* __restrict__ res,
            float* __restrict__ C)
{
    constexpr int BM = 128, BN = 64, BK = 16;
    __shared__ unsigned int Ahs[BK][BM + 8];   // pre-split tf32 hi
    __shared__ unsigned int Als[BK][BM + 8];   // pre-split tf32 lo
    __shared__ unsigned int Whs[BK][BN + 8];
    __shared__ unsigned int Wls[BK][BN + 8];

    const int tid  = threadIdx.x;
    const int lane = tid & 31;
    const int warp = tid >> 5;
    const int wm   = warp >> 1;     // 0..3  (m direction, 32 rows each)
    const int wn   = warp & 1;      // 0..1  (n direction, 32 cols each)
    const int m0   = blockIdx.y * BM;
    const int n0   = blockIdx.x * BN;

    // global loaders: A 128x16 = 512 float4 -> 2/thread; W 64x16 = 256 -> 1/thread
    const float* aptr[2]; int arow[2], akq[2];
#pragma unroll
    for (int i = 0; i < 2; i++) {
        int f = tid + i * 256;
        arow[i] = f >> 2; akq[i] = f & 3;
        int gr = m0 + arow[i];
        if (AMap == AM_SHIFT) gr = map_shift_row(gr);
        aptr[i] = A + (size_t)gr * Kdim + akq[i] * 4;
    }
    const int wrow = tid >> 2, wkq = tid & 3;
    const float* wptr = W + (size_t)(n0 + wrow) * Kdim + wkq * 4;

    float acc[2][4][4] = {};

    float4 av[2], wv;
#pragma unroll
    for (int i = 0; i < 2; i++) av[i] = *reinterpret_cast<const float4*>(aptr[i]);
    wv = *reinterpret_cast<const float4*>(wptr);

    const int r  = lane >> 2;
    const int kq = lane & 3;

    for (int kt = 0; kt < Kdim; kt += BK) {
        // stage current tile, splitting to tf32 hi/lo ONCE per element
#pragma unroll
        for (int i = 0; i < 2; i++) {
            float vv[4] = {av[i].x, av[i].y, av[i].z, av[i].w};
#pragma unroll
            for (int j = 0; j < 4; j++) {
                unsigned int hi, lo; tf32_split(vv[j], hi, lo);
                int k = akq[i] * 4 + j;
                int c = SW(k, arow[i]);
                Ahs[k][c] = hi; Als[k][c] = lo;
            }
        }
        {
            float vv[4] = {wv.x, wv.y, wv.z, wv.w};
#pragma unroll
            for (int j = 0; j < 4; j++) {
                unsigned int hi, lo; tf32_split(vv[j], hi, lo);
                int k = wkq * 4 + j;
                int c = SW(k, wrow);
                Whs[k][c] = hi; Wls[k][c] = lo;
            }
        }
        __syncthreads();

        // prefetch next tile into registers (hidden behind MMA work)
        if (kt + BK < Kdim) {
#pragma unroll
            for (int i = 0; i < 2; i++)
                av[i] = *reinterpret_cast<const float4*>(aptr[i] + kt + BK);
            wv = *reinterpret_cast<const float4*>(wptr + kt + BK);
        }

#pragma unroll
        for (int ks = 0; ks < 2; ks++) {
            const int kk = ks * 8;
            const int kA = kk + kq;       // k>>2 constant per load below
            const int kB = kk + 4 + kq;
            unsigned int ah[2][4], al[2][4], bh[4][2], bl[4][2];
#pragma unroll
            for (int mt = 0; mt < 2; mt++) {
                int mb = wm * 32 + mt * 16 + r;
                ah[mt][0] = Ahs[kA][SW(kA, mb)];
                ah[mt][1] = Ahs[kA][SW(kA, mb + 8)];
                ah[mt][2] = Ahs[kB][SW(kB, mb)];
                ah[mt][3] = Ahs[kB][SW(kB, mb + 8)];
                al[mt][0] = Als[kA][SW(kA, mb)];
                al[mt][1] = Als[kA][SW(kA, mb + 8)];
                al[mt][2] = Als[kB][SW(kB, mb)];
                al[mt][3] = Als[kB][SW(kB, mb + 8)];
            }
#pragma unroll
            for (int nt = 0; nt < 4; nt++) {
                int nb = wn * 32 + nt * 8 + r;
                bh[nt][0] = Whs[kA][SW(kA, nb)];
                bh[nt][1] = Whs[kB][SW(kB, nb)];
                bl[nt][0] = Wls[kA][SW(kA, nb)];
                bl[nt][1] = Wls[kB][SW(kB, nb)];
            }
#pragma unroll
            for (int mt = 0; mt < 2; mt++)
#pragma unroll
                for (int nt = 0; nt < 4; nt++) {
                    MMA_TF32(acc[mt][nt], ah[mt][0], ah[mt][1], ah[mt][2], ah[mt][3],
                             bh[nt][0], bh[nt][1]);
                    MMA_TF32(acc[mt][nt], ah[mt][0], ah[mt][1], ah[mt][2], ah[mt][3],
                             bl[nt][0], bl[nt][1]);
                    MMA_TF32(acc[mt][nt], al[mt][0], al[mt][1], al[mt][2], al[mt][3],
                             bh[nt][0], bh[nt][1]);
                }
        }
        __syncthreads();
    }

    // ----------------------------- epilogue --------------------------------
#pragma unroll
    for (int nt = 0; nt < 4; nt++) {
        const int col = n0 + wn * 32 + nt * 8 + (lane & 3) * 2;
        const float b0v = bias[col], b1v = bias[col + 1];
#pragma unroll
        for (int mt = 0; mt < 2; mt++) {
#pragma unroll
            for (int half = 0; half < 2; half++) {
                int m = m0 + wm * 32 + mt * 16 + (lane >> 2) + half * 8;
                float v0 = acc[mt][nt][half * 2 + 0] + b0v;
                float v1 = acc[mt][nt][half * 2 + 1] + b1v;
                if (Epi == EPI_GELU) {
                    v0 = 0.5f * v0 * (1.f + erff(v0 * 0.70710678118654752f));
                    v1 = 0.5f * v1 * (1.f + erff(v1 * 0.70710678118654752f));
                }
                int outrow = (Epi == EPI_RES_SCATTER) ? map_shift_row(m) : m;
                float* cp = C + (size_t)outrow * Ndim + col;
                if (Epi == EPI_RES_SCATTER || Epi == EPI_RES_DIRECT) {
                    float2 rr = *reinterpret_cast<const float2*>(
                        res + (size_t)outrow * Ndim + col);
                    v0 += rr.x; v1 += rr.y;
                }
                *reinterpret_cast<float2*>(cp) = make_float2(v0, v1);
            }
        }
    }
}

// --------------------------- Attention -------------------------------------
// one 64-thread block per (window, head); thread = query row n
__global__ void __launch_bounds__(64)
attn_kernel(const float* __restrict__ qkv, const float* __restrict__ rpb,
            float* __restrict__ out)
{
    __shared__ float Ksm[64][36];
    __shared__ float Vsm[64][36];
    __shared__ float bsm[1350];      // 225 * 6

    const int head = blockIdx.x % HEADS;
    const int win  = blockIdx.x / HEADS;
    const int n    = threadIdx.x;

    for (int i = n; i < 1350; i += 64) bsm[i] = rpb[i];

    const float* base = qkv + (size_t)win * 64 * QKVDIM;
    const float* qp = base + n * QKVDIM + head * HD;
    const float* kp = qp + CDIM;
    const float* vp = qp + 2 * CDIM;

    float q[32];
#pragma unroll
    for (int d4 = 0; d4 < 8; d4++) {
        float4 kv = *reinterpret_cast<const float4*>(kp + d4 * 4);
        Ksm[n][d4 * 4 + 0] = kv.x; Ksm[n][d4 * 4 + 1] = kv.y;
        Ksm[n][d4 * 4 + 2] = kv.z; Ksm[n][d4 * 4 + 3] = kv.w;
        float4 vv = *reinterpret_cast<const float4*>(vp + d4 * 4);
        Vsm[n][d4 * 4 + 0] = vv.x; Vsm[n][d4 * 4 + 1] = vv.y;
        Vsm[n][d4 * 4 + 2] = vv.z; Vsm[n][d4 * 4 + 3] = vv.w;
        float4 qq = *reinterpret_cast<const float4*>(qp + d4 * 4);
        q[d4 * 4 + 0] = qq.x * SCALE; q[d4 * 4 + 1] = qq.y * SCALE;
        q[d4 * 4 + 2] = qq.z * SCALE; q[d4 * 4 + 3] = qq.w * SCALE;
    }
    __syncthreads();

    const int wi = win & 255, wh = wi >> 4, ww = wi & 15;
    const int i1 = n >> 3, j1 = n & 7;
    const int rh1 = (wh == 15) ? ((i1 < 4) ? 1 : 2) : 0;
    const int rw1 = (ww == 15) ? ((j1 < 4) ? 1 : 2) : 0;

    float s[64];
#pragma unroll
    for (int m = 0; m < 64; m++) {
        float dot = 0.f;
#pragma unroll
        for (int d4 = 0; d4 < 8; d4++) {
            float4 kk = *reinterpret_cast<const float4*>(&Ksm[m][d4 * 4]);
            dot = fmaf(q[d4 * 4 + 0], kk.x, dot);
            dot = fmaf(q[d4 * 4 + 1], kk.y, dot);
            dot = fmaf(q[d4 * 4 + 2], kk.z, dot);
            dot = fmaf(q[d4 * 4 + 3], kk.w, dot);
        }
        const int i2 = m >> 3, j2 = m & 7;
        float bias = bsm[((i1 - i2 + 7) * 15 + (j1 - j2 + 7)) * HEADS + head];
        const int rh2 = (wh == 15) ? ((i2 < 4) ? 1 : 2) : 0;
        const int rw2 = (ww == 15) ? ((j2 < 4) ? 1 : 2) : 0;
        float msk = (rh1 == rh2 && rw1 == rw2) ? 0.f : -100.f;
        s[m] = dot + bias + msk;
    }

    float mx = -1e30f;
#pragma unroll
    for (int m = 0; m < 64; m++) mx = fmaxf(mx, s[m]);
    float sum = 0.f;
#pragma unroll
    for (int m = 0; m < 64; m++) { s[m] = __expf(s[m] - mx); sum += s[m]; }
    float inv = 1.f / sum;

    float o[32] = {};
#pragma unroll
    for (int m = 0; m < 64; m++) {
        float p = s[m] * inv;
#pragma unroll
        for (int d4 = 0; d4 < 8; d4++) {
            float4 vv = *reinterpret_cast<const float4*>(&Vsm[m][d4 * 4]);
            o[d4 * 4 + 0] = fmaf(p, vv.x, o[d4 * 4 + 0]);
            o[d4 * 4 + 1] = fmaf(p, vv.y, o[d4 * 4 + 1]);
            o[d4 * 4 + 2] = fmaf(p, vv.z, o[d4 * 4 + 2]);
            o[d4 * 4 + 3] = fmaf(p, vv.w, o[d4 * 4 + 3]);
        }
    }

    float* op = out + (size_t)(win * 64 + n) * CDIM + head * HD;
#pragma unroll
    for (int d4 = 0; d4 < 8; d4++)
        *reinterpret_cast<float4*>(op + d4 * 4) =
            make_float4(o[d4 * 4 + 0], o[d4 * 4 + 1], o[d4 * 4 + 2], o[d4 * 4 + 3]);
}

// ---------------------------------------------------------------------------
extern "C" void kernel_launch(void* const* d_in, const int* in_sizes, int n_in,
                              void* d_out, int out_size)
{
    const float* x       = (const float*)d_in[0];
    const float* norm1_g = (const float*)d_in[1];
    const float* norm1_b = (const float*)d_in[2];
    const float* qkv_w   = (const float*)d_in[3];
    const float* qkv_b   = (const float*)d_in[4];
    const float* proj_w  = (const float*)d_in[5];
    const float* proj_b  = (const float*)d_in[6];
    const float* rpb     = (const float*)d_in[7];
    const float* norm2_g = (const float*)d_in[8];
    const float* norm2_b = (const float*)d_in[9];
    const float* fc1_w   = (const float*)d_in[10];
    const float* fc1_b   = (const float*)d_in[11];
    const float* fc2_w   = (const float*)d_in[12];
    const float* fc2_b   = (const float*)d_in[13];
    float* out = (float*)d_out;

    float *p_ln, *p_qkv, *p_attn, *p_h, *p_m1;
    cudaGetSymbolAddress((void**)&p_ln,   g_ln);
    cudaGetSymbolAddress((void**)&p_qkv,  g_qkv);
    cudaGetSymbolAddress((void**)&p_attn, g_attn);
    cudaGetSymbolAddress((void**)&p_h,    g_h);
    cudaGetSymbolAddress((void**)&p_m1,   g_m1);

    const dim3 gemmBlk(256);
    const dim3 gridQKV(QKVDIM / 64, TOKENS / 128);
    const dim3 gridC  (CDIM   / 64, TOKENS / 128);
    const dim3 gridM  (MLPDIM / 64, TOKENS / 128);

    // 1. LN1
    ln_kernel<<<TOKENS / 8, 256>>>(x, norm1_g, norm1_b, p_ln);
    // 2. QKV gemm with shifted-window row gather
    gemm_kernel<CDIM, QKVDIM, AM_SHIFT, EPI_BIAS>
        <<<gridQKV, gemmBlk>>>(p_ln, qkv_w, qkv_b, nullptr, p_qkv);
    // 3. windowed attention (bias + shift mask + softmax)
    attn_kernel<<<NWIN * HEADS, 64>>>(p_qkv, rpb, p_attn);
    // 4. proj gemm; scatter rows back (window reverse + roll) + shortcut residual
    gemm_kernel<CDIM, CDIM, AM_DIRECT, EPI_RES_SCATTER>
        <<<gridC, gemmBlk>>>(p_attn, proj_w, proj_b, x, p_h);
    // 5. LN2
    ln_kernel<<<TOKENS / 8, 256>>>(p_h, norm2_g, norm2_b, p_ln);
    // 6. FC1 + exact GELU
    gemm_kernel<CDIM, MLPDIM, AM_DIRECT, EPI_GELU>
        <<<gridM, gemmBlk>>>(p_ln, fc1_w, fc1_b, nullptr, p_m1);
    // 7. FC2 + residual h  -> d_out
    gemm_kernel<MLPDIM, CDIM, AM_DIRECT, EPI_RES_DIRECT>
        <<<gridC, gemmBlk>>>(p_m1, fc2_w, fc2_b, p_h, out);
}